// round 7
// baseline (speedup 1.0000x reference)
#include <cuda_runtime.h>
#include <stdint.h>

// ---------------------------------------------------------------------------
// ClipperEventEncoder: LIF recurrence (tau=2, v_th=1, hard reset) ->
// conv3x3(1->4)+relu -> conv3x3(4->1)+relu -> mean over T.
//
// Single fused launch. Blocks [0,1024) = LIF streaming pass (memory-floor
// loop: 2 px/thread, 16-load register batches, ballots only in the rare
// spike path). Blocks [1024,1280) = one conv block per 32x32 output tile:
// preload weights, spin on a device counter until all LIF blocks arrive
// (deadlock-free by residency counting: 256 spinning conv blocks < 1184
// resident slots at 25.7 KB smem/block, so LIF blocks always schedule and
// retire), then per-timestep spike skip + shared-memory conv + mean + store.
//
// With x ~ U[0,1) the membrane potential v=(v+x)/2 stays < 1 forever
// (exactly in fp32: near threshold x-v is Sterbenz-exact and the sum is
// <= 1-2^-24), so zero spikes: conv blocks skip all 96 steps and write the
// 1 MB of zeros. The conv path remains fully correct for arbitrary inputs.
// ---------------------------------------------------------------------------

#define IMG_H 512
#define IMG_W 512
#define HW (IMG_H * IMG_W)
#define T_STEPS 96
#define WPR (IMG_W / 32)                 // 16 mask words per image row
#define NWORDS (IMG_H * WPR)             // 8192 words per time step

#define LIF_BLOCKS 1024
#define CONV_BLOCKS 256
#define TOTAL_BLOCKS (LIF_BLOCKS + CONV_BLOCKS)

// Mask layout: [word][t]  (word-major so per-warp zero fill is coalesced)
__device__ uint32_t g_spike_mask[NWORDS * T_STEPS];   // 3.1 MB
// Per-word timestep summary, padded to 16 B: (any_t0..31, any_t32..63,
// any_t64..95, 0). Written unconditionally by every warp -> no init pass.
__device__ uint4 g_word_any4[NWORDS];                 // 128 KB
// Grid handoff counter. Zero at module load; the final (1280th) increment's
// observer resets it to 0, so every graph replay starts from 0.
__device__ unsigned int g_sync;

#define TILE 32
#define SREG 36          // spike region edge (TILE + 4)
#define HREG 34          // h region edge     (TILE + 2)

__global__ void __launch_bounds__(128)
fused_kernel(const float* __restrict__ x,
             const float* __restrict__ w1,    // [4,1,3,3]
             const float* __restrict__ w2,    // [1,4,3,3]
             float* __restrict__ out)         // [512,512]
{
    __shared__ uint32_t sany[4];
    __shared__ float    ssp[SREG][SREG + 4];
    __shared__ float    sh[4][HREG][HREG + 2];
    __shared__ float    sw1[36];
    __shared__ float    sw2[36];

    const int bid = blockIdx.x;
    const int tid = threadIdx.x;

    // =====================================================================
    // LIF path: blocks [0, 1024)
    // =====================================================================
    if (bid < LIF_BLOCKS) {
        const int lane  = tid & 31;
        const int gw    = bid * 4 + (tid >> 5);          // global warp id
        const int seg   = gw * 64;
        const int pxA   = seg + lane;
        const int pxB   = pxA + 32;
        const int wordA = gw * 2;
        const int wordB = wordA + 1;

        float vA = 0.0f, vB = 0.0f;
        uint32_t bitsA[3], bitsB[3];

        // Fully unrolled: compile-time shifts, ptxas front-batches each
        // 16-load group -> MLP ~ 16, DRAM-bound.
        #pragma unroll
        for (int c = 0; c < 3; ++c) {
            uint32_t aA = 0u, aB = 0u;
            #pragma unroll
            for (int tb = 0; tb < 32; tb += 8) {
                const float* __restrict__ base = x + (size_t)(c * 32 + tb) * HW;
                float ra[8], rb[8];
                #pragma unroll
                for (int j = 0; j < 8; ++j) {
                    ra[j] = __ldcs(base + (size_t)j * HW + pxA);
                    rb[j] = __ldcs(base + (size_t)j * HW + pxB);
                }
                #pragma unroll
                for (int j = 0; j < 8; ++j) {
                    vA = vA + (ra[j] - vA) * 0.5f;           // v + (x-v)/tau
                    const uint32_t sA = (vA >= 1.0f) ? 1u : 0u;
                    aA |= sA << (tb + j);
                    if (sA) vA = 0.0f;                       // hard reset

                    vB = vB + (rb[j] - vB) * 0.5f;
                    const uint32_t sB = (vB >= 1.0f) ? 1u : 0u;
                    aB |= sB << (tb + j);
                    if (sB) vB = 0.0f;
                }
            }
            bitsA[c] = aA;
            bitsB[c] = aB;
        }

        uint32_t anyA[3], anyB[3];
        #pragma unroll
        for (int c = 0; c < 3; ++c) {
            anyA[c] = __reduce_or_sync(0xffffffffu, bitsA[c]);
            anyB[c] = __reduce_or_sync(0xffffffffu, bitsB[c]);
        }
        if (lane == 0) {
            g_word_any4[wordA] = make_uint4(anyA[0], anyA[1], anyA[2], 0u);
            g_word_any4[wordB] = make_uint4(anyB[0], anyB[1], anyB[2], 0u);
        }

        uint32_t* wA = &g_spike_mask[(size_t)wordA * T_STEPS];
        uint32_t* wB = &g_spike_mask[(size_t)wordB * T_STEPS];

        const uint32_t spA = anyA[0] | anyA[1] | anyA[2];    // warp-uniform
        const uint32_t spB = anyB[0] | anyB[1] | anyB[2];

        if (spA == 0u) {           // common case: coalesced zero column
            __stcs(&wA[lane], 0u); __stcs(&wA[lane + 32], 0u); __stcs(&wA[lane + 64], 0u);
        } else {
            #pragma unroll 1
            for (int t = 0; t < T_STEPS; ++t) {
                const int c = t >> 5, s = t & 31;
                uint32_t m = 0u;
                if ((anyA[c] >> s) & 1u)                      // warp-uniform guard
                    m = __ballot_sync(0xffffffffu, (bitsA[c] >> s) & 1u);
                if (lane == 0) wA[t] = m;
            }
        }
        if (spB == 0u) {
            __stcs(&wB[lane], 0u); __stcs(&wB[lane + 32], 0u); __stcs(&wB[lane + 64], 0u);
        } else {
            #pragma unroll 1
            for (int t = 0; t < T_STEPS; ++t) {
                const int c = t >> 5, s = t & 31;
                uint32_t m = 0u;
                if ((anyB[c] >> s) & 1u)
                    m = __ballot_sync(0xffffffffu, (bitsB[c] >> s) & 1u);
                if (lane == 0) wB[t] = m;
            }
        }

        // Publish: all this block's writes, then count in.
        __syncthreads();
        __threadfence();
        if (tid == 0) atomicAdd(&g_sync, 1u);
        return;
    }

    // =====================================================================
    // Conv path: blocks [1024, 1280), one per 32x32 output tile.
    // =====================================================================
    const int tile = bid - LIF_BLOCKS;
    const int txb  = tile & 15;
    const int tyb  = tile >> 4;
    const int x0   = txb * TILE;
    const int y0   = tyb * TILE;
    const int wx0  = x0 >> 5;

    // Independent of LIF output: preload weights while waiting.
    if (tid < 36) { sw1[tid] = w1[tid]; sw2[tid] = w2[tid]; }
    if (tid < 4)  sany[tid] = 0u;

    // Wait for all LIF blocks. Deadlock-free: 256 spinning conv blocks can
    // never fill the >=1184 resident-block slots, so LIF blocks always run.
    if (tid == 0) {
        while (*(volatile unsigned int*)&g_sync < (unsigned)LIF_BLOCKS)
            __nanosleep(256);
    }
    __syncthreads();
    __threadfence();

    // ---- Phase A: OR halo per-word summaries (one LDG.128 each) ----------
    // Words covering columns [x0-32, x0+63] x rows [y0-2, y0+33]: superset
    // of the true 2-px halo. 36 rows x 3 word-cols.
    {
        uint32_t l0 = 0u, l1 = 0u, l2 = 0u;
        for (int i = tid; i < 36 * 3; i += 128) {
            const int r   = i / 3;
            const int wxo = i % 3 - 1;
            const int gy  = y0 - 2 + r;
            const int wx  = wx0 + wxo;
            if (gy >= 0 && gy < IMG_H && wx >= 0 && wx < WPR) {
                const uint4 a = __ldcg(&g_word_any4[gy * WPR + wx]);
                l0 |= a.x; l1 |= a.y; l2 |= a.z;
            }
        }
        if (l0) atomicOr(&sany[0], l0);
        if (l1) atomicOr(&sany[1], l1);
        if (l2) atomicOr(&sany[2], l2);
    }
    __syncthreads();

    const uint32_t a0 = sany[0], a1 = sany[1], a2 = sany[2];

    float acc[8];
    #pragma unroll
    for (int k = 0; k < 8; ++k) acc[k] = 0.0f;

    if (a0 | a1 | a2) {
        for (int t = 0; t < T_STEPS; ++t) {
            const uint32_t chunk = (t < 32) ? a0 : (t < 64) ? a1 : a2;
            if (!((chunk >> (t & 31)) & 1u)) continue;       // uniform branch

            // ---- decode spike bits -> float tile (zero-padded at edges) ---
            for (int i = tid; i < SREG * SREG; i += 128) {
                const int yy = i / SREG, xx = i % SREG;
                const int gy = y0 - 2 + yy, gx = x0 - 2 + xx;
                float s = 0.0f;
                if (gy >= 0 && gy < IMG_H && gx >= 0 && gx < IMG_W) {
                    const int w = gy * WPR + (gx >> 5);
                    const uint32_t m = __ldcg(&g_spike_mask[(size_t)w * T_STEPS + t]);
                    s = ((m >> (gx & 31)) & 1u) ? 1.0f : 0.0f;
                }
                ssp[yy][xx] = s;
            }
            __syncthreads();

            // ---- conv1 (1->4) + relu over the 34x34 h region --------------
            for (int i = tid; i < HREG * HREG; i += 128) {
                const int hy = i / HREG, hx = i % HREG;
                float b0 = 0.f, b1 = 0.f, b2 = 0.f, b3 = 0.f;
                #pragma unroll
                for (int ky = 0; ky < 3; ++ky) {
                    #pragma unroll
                    for (int kx = 0; kx < 3; ++kx) {
                        const float s = ssp[hy + ky][hx + kx];
                        const int  k = ky * 3 + kx;
                        b0 += sw1[ 0 + k] * s;
                        b1 += sw1[ 9 + k] * s;
                        b2 += sw1[18 + k] * s;
                        b3 += sw1[27 + k] * s;
                    }
                }
                sh[0][hy][hx] = fmaxf(b0, 0.f);
                sh[1][hy][hx] = fmaxf(b1, 0.f);
                sh[2][hy][hx] = fmaxf(b2, 0.f);
                sh[3][hy][hx] = fmaxf(b3, 0.f);
            }
            __syncthreads();

            // ---- conv2 (4->1) + relu, accumulate (8 outputs/thread) -------
            #pragma unroll
            for (int k = 0; k < 8; ++k) {
                const int o  = tid + 128 * k;
                const int oy = o >> 5;
                const int ox = o & 31;
                float a = 0.0f;
                #pragma unroll
                for (int c = 0; c < 4; ++c) {
                    #pragma unroll
                    for (int ky = 0; ky < 3; ++ky) {
                        #pragma unroll
                        for (int kx = 0; kx < 3; ++kx) {
                            a += sw2[c * 9 + ky * 3 + kx] * sh[c][oy + ky][ox + kx];
                        }
                    }
                }
                acc[k] += fmaxf(a, 0.0f);
            }
            __syncthreads();   // sh reused next iteration after decode barrier
        }
    }

    // ---- mean over T and store -------------------------------------------
    const float inv_t = 1.0f / (float)T_STEPS;
    #pragma unroll
    for (int k = 0; k < 8; ++k) {
        const int o  = tid + 128 * k;
        const int oy = o >> 5;
        const int ox = o & 31;
        out[(size_t)(y0 + oy) * IMG_W + (x0 + ox)] = acc[k] * inv_t;
    }

    // Count out; the last conv block resets the counter for the next launch.
    __syncthreads();
    if (tid == 0) {
        const unsigned old = atomicAdd(&g_sync, 1u);
        if (old == (unsigned)(TOTAL_BLOCKS - 1))
            *(volatile unsigned int*)&g_sync = 0u;
    }
}

// ---------------------------------------------------------------------------
extern "C" void kernel_launch(void* const* d_in, const int* in_sizes, int n_in,
                              void* d_out, int out_size)
{
    const float* x_seq = (const float*)d_in[0];   // [96, 512, 512] fp32
    const float* w1    = (const float*)d_in[1];   // [4,1,3,3] fp32
    const float* w2    = (const float*)d_in[2];   // [1,4,3,3] fp32
    float*       out   = (float*)d_out;           // [512,512] fp32

    fused_kernel<<<TOTAL_BLOCKS, 128>>>(x_seq, w1, w2, out);
}

// round 8
// speedup vs baseline: 1.0384x; 1.0384x over previous
#include <cuda_runtime.h>
#include <stdint.h>

// ---------------------------------------------------------------------------
// ClipperEventEncoder: LIF recurrence (tau=2, v_th=1, hard reset) ->
// conv3x3(1->4)+relu -> conv3x3(4->1)+relu -> mean over T.
//
// R8: single launch, 1024 blocks, "last finishers do the epilogue".
//  - ALL blocks first run the LIF streaming pass (2 px/thread, 16-load
//    register batches, ballots only in the rare spike path). Single wave
//    (1024 blocks < ~1184 resident slots at 25.7 KB smem/block), so no
//    slot is ever occupied by a waiting block during the bandwidth phase
//    (this was R7's regression: spinners displaced LIF blocks into a
//    straggler mini-wave).
//  - On completion each block takes a ticket. The last 256 finishers each
//    own one 32x32 conv tile: spin (briefly -- they ARE the late blocks)
//    until all 1024 LIF arrivals, then per-timestep spike skip +
//    shared-memory conv + mean + store. Other blocks exit, freeing SMs.
//  - Counters self-reset (g_done==255 observer) -> deterministic per
//    graph replay.
//
// With x ~ U[0,1) the membrane potential v=(v+x)/2 stays < 1 forever
// (exactly in fp32: near threshold x-v is Sterbenz-exact and the sum is
// <= 1-2^-24), so zero spikes: conv tiles skip all 96 steps and write the
// 1 MB of zeros. The conv path remains fully correct for arbitrary inputs.
// ---------------------------------------------------------------------------

#define IMG_H 512
#define IMG_W 512
#define HW (IMG_H * IMG_W)
#define T_STEPS 96
#define WPR (IMG_W / 32)                 // 16 mask words per image row
#define NWORDS (IMG_H * WPR)             // 8192 words per time step

#define NBLOCKS 1024
#define CONV_TILES 256
#define FIRST_CONV_TICKET (NBLOCKS - CONV_TILES)   // 768

// Mask layout: [word][t]  (word-major so per-warp zero fill is coalesced)
__device__ uint32_t g_spike_mask[NWORDS * T_STEPS];   // 3.1 MB
// Per-word timestep summary, padded to 16 B: (any_t0..31, any_t32..63,
// any_t64..95, 0). Written unconditionally by every warp -> no init pass.
__device__ uint4 g_word_any4[NWORDS];                 // 128 KB
// Handoff counters. Zero at module load; reset by the g_done==255 observer
// at the end of every execution -> each graph replay starts from 0.
__device__ unsigned int g_sync;   // LIF completions (0 -> 1024)
__device__ unsigned int g_done;   // conv-tile completions (0 -> 256)

#define TILE 32
#define SREG 36          // spike region edge (TILE + 4)
#define HREG 34          // h region edge     (TILE + 2)

__global__ void __launch_bounds__(128)
fused_kernel(const float* __restrict__ x,
             const float* __restrict__ w1,    // [4,1,3,3]
             const float* __restrict__ w2,    // [1,4,3,3]
             float* __restrict__ out)         // [512,512]
{
    __shared__ unsigned sticket;
    __shared__ uint32_t sany[4];
    __shared__ float    ssp[SREG][SREG + 4];
    __shared__ float    sh[4][HREG][HREG + 2];
    __shared__ float    sw1[36];
    __shared__ float    sw2[36];

    const int bid = blockIdx.x;
    const int tid = threadIdx.x;

    // =====================================================================
    // Phase 1: LIF streaming pass (every block).
    // =====================================================================
    {
        const int lane  = tid & 31;
        const int gw    = bid * 4 + (tid >> 5);          // global warp id
        const int seg   = gw * 64;
        const int pxA   = seg + lane;
        const int pxB   = pxA + 32;
        const int wordA = gw * 2;
        const int wordB = wordA + 1;

        float vA = 0.0f, vB = 0.0f;
        uint32_t bitsA[3], bitsB[3];

        // Fully unrolled: compile-time shifts, ptxas front-batches each
        // 16-load group -> MLP ~ 16, DRAM-bound.
        #pragma unroll
        for (int c = 0; c < 3; ++c) {
            uint32_t aA = 0u, aB = 0u;
            #pragma unroll
            for (int tb = 0; tb < 32; tb += 8) {
                const float* __restrict__ base = x + (size_t)(c * 32 + tb) * HW;
                float ra[8], rb[8];
                #pragma unroll
                for (int j = 0; j < 8; ++j) {
                    ra[j] = __ldcs(base + (size_t)j * HW + pxA);
                    rb[j] = __ldcs(base + (size_t)j * HW + pxB);
                }
                #pragma unroll
                for (int j = 0; j < 8; ++j) {
                    vA = vA + (ra[j] - vA) * 0.5f;           // v + (x-v)/tau
                    const uint32_t sA = (vA >= 1.0f) ? 1u : 0u;
                    aA |= sA << (tb + j);
                    if (sA) vA = 0.0f;                       // hard reset

                    vB = vB + (rb[j] - vB) * 0.5f;
                    const uint32_t sB = (vB >= 1.0f) ? 1u : 0u;
                    aB |= sB << (tb + j);
                    if (sB) vB = 0.0f;
                }
            }
            bitsA[c] = aA;
            bitsB[c] = aB;
        }

        uint32_t anyA[3], anyB[3];
        #pragma unroll
        for (int c = 0; c < 3; ++c) {
            anyA[c] = __reduce_or_sync(0xffffffffu, bitsA[c]);
            anyB[c] = __reduce_or_sync(0xffffffffu, bitsB[c]);
        }
        if (lane == 0) {
            g_word_any4[wordA] = make_uint4(anyA[0], anyA[1], anyA[2], 0u);
            g_word_any4[wordB] = make_uint4(anyB[0], anyB[1], anyB[2], 0u);
        }

        uint32_t* wA = &g_spike_mask[(size_t)wordA * T_STEPS];
        uint32_t* wB = &g_spike_mask[(size_t)wordB * T_STEPS];

        const uint32_t spA = anyA[0] | anyA[1] | anyA[2];    // warp-uniform
        const uint32_t spB = anyB[0] | anyB[1] | anyB[2];

        if (spA == 0u) {           // common case: coalesced zero column
            __stcs(&wA[lane], 0u); __stcs(&wA[lane + 32], 0u); __stcs(&wA[lane + 64], 0u);
        } else {
            #pragma unroll 1
            for (int t = 0; t < T_STEPS; ++t) {
                const int c = t >> 5, s = t & 31;
                uint32_t m = 0u;
                if ((anyA[c] >> s) & 1u)                      // warp-uniform guard
                    m = __ballot_sync(0xffffffffu, (bitsA[c] >> s) & 1u);
                if (lane == 0) wA[t] = m;
            }
        }
        if (spB == 0u) {
            __stcs(&wB[lane], 0u); __stcs(&wB[lane + 32], 0u); __stcs(&wB[lane + 64], 0u);
        } else {
            #pragma unroll 1
            for (int t = 0; t < T_STEPS; ++t) {
                const int c = t >> 5, s = t & 31;
                uint32_t m = 0u;
                if ((anyB[c] >> s) & 1u)
                    m = __ballot_sync(0xffffffffu, (bitsB[c] >> s) & 1u);
                if (lane == 0) wB[t] = m;
            }
        }
    }

    // ---- Publish this block's writes, take a ticket ----------------------
    __syncthreads();
    __threadfence();
    if (tid == 0) sticket = atomicAdd(&g_sync, 1u);
    __syncthreads();
    const unsigned ticket = sticket;

    if (ticket < FIRST_CONV_TICKET) return;   // early finishers exit, free SMs

    // =====================================================================
    // Phase 2: conv epilogue (last 256 finishers, one 32x32 tile each).
    // =====================================================================
    const int tile = (int)(ticket - FIRST_CONV_TICKET);
    const int x0   = (tile & 15) * TILE;
    const int y0   = (tile >> 4) * TILE;
    const int wx0  = x0 >> 5;

    if (tid < 36) { sw1[tid] = w1[tid]; sw2[tid] = w2[tid]; }
    if (tid < 4)  sany[tid] = 0u;

    // Wait for remaining LIF arrivals. We're among the LAST finishers, so
    // this is just the block-completion skew; the blocks being waited on
    // are resident and running (single wave) -> no deadlock possible.
    if (tid == 0) {
        while (*(volatile unsigned int*)&g_sync < (unsigned)NBLOCKS)
            __nanosleep(64);
    }
    __syncthreads();
    __threadfence();

    // ---- Phase A: OR halo per-word summaries (one LDG.128 each) ----------
    // Words covering columns [x0-32, x0+63] x rows [y0-2, y0+33]: superset
    // of the true 2-px halo (never skips a needed step).
    {
        uint32_t l0 = 0u, l1 = 0u, l2 = 0u;
        for (int i = tid; i < 36 * 3; i += 128) {
            const int r   = i / 3;
            const int wxo = i % 3 - 1;
            const int gy  = y0 - 2 + r;
            const int wx  = wx0 + wxo;
            if (gy >= 0 && gy < IMG_H && wx >= 0 && wx < WPR) {
                const uint4 a = __ldcg(&g_word_any4[gy * WPR + wx]);
                l0 |= a.x; l1 |= a.y; l2 |= a.z;
            }
        }
        if (l0) atomicOr(&sany[0], l0);
        if (l1) atomicOr(&sany[1], l1);
        if (l2) atomicOr(&sany[2], l2);
    }
    __syncthreads();

    const uint32_t a0 = sany[0], a1 = sany[1], a2 = sany[2];

    float acc[8];
    #pragma unroll
    for (int k = 0; k < 8; ++k) acc[k] = 0.0f;

    if (a0 | a1 | a2) {
        for (int t = 0; t < T_STEPS; ++t) {
            const uint32_t chunk = (t < 32) ? a0 : (t < 64) ? a1 : a2;
            if (!((chunk >> (t & 31)) & 1u)) continue;       // uniform branch

            // ---- decode spike bits -> float tile (zero-padded at edges) ---
            for (int i = tid; i < SREG * SREG; i += 128) {
                const int yy = i / SREG, xx = i % SREG;
                const int gy = y0 - 2 + yy, gx = x0 - 2 + xx;
                float s = 0.0f;
                if (gy >= 0 && gy < IMG_H && gx >= 0 && gx < IMG_W) {
                    const int w = gy * WPR + (gx >> 5);
                    const uint32_t m = __ldcg(&g_spike_mask[(size_t)w * T_STEPS + t]);
                    s = ((m >> (gx & 31)) & 1u) ? 1.0f : 0.0f;
                }
                ssp[yy][xx] = s;
            }
            __syncthreads();

            // ---- conv1 (1->4) + relu over the 34x34 h region --------------
            for (int i = tid; i < HREG * HREG; i += 128) {
                const int hy = i / HREG, hx = i % HREG;
                float b0 = 0.f, b1 = 0.f, b2 = 0.f, b3 = 0.f;
                #pragma unroll
                for (int ky = 0; ky < 3; ++ky) {
                    #pragma unroll
                    for (int kx = 0; kx < 3; ++kx) {
                        const float s = ssp[hy + ky][hx + kx];
                        const int  k = ky * 3 + kx;
                        b0 += sw1[ 0 + k] * s;
                        b1 += sw1[ 9 + k] * s;
                        b2 += sw1[18 + k] * s;
                        b3 += sw1[27 + k] * s;
                    }
                }
                sh[0][hy][hx] = fmaxf(b0, 0.f);
                sh[1][hy][hx] = fmaxf(b1, 0.f);
                sh[2][hy][hx] = fmaxf(b2, 0.f);
                sh[3][hy][hx] = fmaxf(b3, 0.f);
            }
            __syncthreads();

            // ---- conv2 (4->1) + relu, accumulate (8 outputs/thread) -------
            #pragma unroll
            for (int k = 0; k < 8; ++k) {
                const int o  = tid + 128 * k;
                const int oy = o >> 5;
                const int ox = o & 31;
                float a = 0.0f;
                #pragma unroll
                for (int c = 0; c < 4; ++c) {
                    #pragma unroll
                    for (int ky = 0; ky < 3; ++ky) {
                        #pragma unroll
                        for (int kx = 0; kx < 3; ++kx) {
                            a += sw2[c * 9 + ky * 3 + kx] * sh[c][oy + ky][ox + kx];
                        }
                    }
                }
                acc[k] += fmaxf(a, 0.0f);
            }
            __syncthreads();   // sh reused next iteration after decode barrier
        }
    }

    // ---- mean over T and store -------------------------------------------
    const float inv_t = 1.0f / (float)T_STEPS;
    #pragma unroll
    for (int k = 0; k < 8; ++k) {
        const int o  = tid + 128 * k;
        const int oy = o >> 5;
        const int ox = o & 31;
        out[(size_t)(y0 + oy) * IMG_W + (x0 + ox)] = acc[k] * inv_t;
    }

    // ---- count out; last conv tile resets counters for the next replay ---
    __syncthreads();
    if (tid == 0) {
        const unsigned old = atomicAdd(&g_done, 1u);
        if (old == (unsigned)(CONV_TILES - 1)) {
            *(volatile unsigned int*)&g_sync = 0u;
            *(volatile unsigned int*)&g_done = 0u;
        }
    }
}

// ---------------------------------------------------------------------------
extern "C" void kernel_launch(void* const* d_in, const int* in_sizes, int n_in,
                              void* d_out, int out_size)
{
    const float* x_seq = (const float*)d_in[0];   // [96, 512, 512] fp32
    const float* w1    = (const float*)d_in[1];   // [4,1,3,3] fp32
    const float* w2    = (const float*)d_in[2];   // [1,4,3,3] fp32
    float*       out   = (float*)d_out;           // [512,512] fp32

    fused_kernel<<<NBLOCKS, 128>>>(x_seq, w1, w2, out);
}